// round 1
// baseline (speedup 1.0000x reference)
#include <cuda_runtime.h>

#define N_TOK 65536
#define D 256
#define K 1024
#define B_ 16
#define HW 4096

// Scratch (static device arrays: allocation-free per harness rules)
__device__ float g_zf[N_TOK * D];   // 64 MB: z transposed to [N, D]
__device__ float g_sz[N_TOK];       // ||z_n||^2
__device__ float g_en[K];           // ||e_k||^2
__device__ int   g_idx[N_TOK];      // argmin indices

// ---------------------------------------------------------------------------
// Kernel 1: NCHW -> [N, D] transpose (per batch: [C, HW] -> [HW, C])
// ---------------------------------------------------------------------------
__global__ void k_transpose(const float* __restrict__ z) {
    __shared__ float tile[32][33];
    int b   = blockIdx.z;
    int c0  = blockIdx.y * 32;
    int hw0 = blockIdx.x * 32;
    int tx = threadIdx.x, ty = threadIdx.y;   // 32 x 8
    const float* zp = z + (size_t)b * D * HW;
#pragma unroll
    for (int j = 0; j < 4; j++) {
        int c = c0 + ty + j * 8;
        tile[ty + j * 8][tx] = zp[(size_t)c * HW + hw0 + tx];
    }
    __syncthreads();
#pragma unroll
    for (int j = 0; j < 4; j++) {
        int n = b * HW + hw0 + ty + j * 8;
        g_zf[(size_t)n * D + c0 + tx] = tile[tx][ty + j * 8];
    }
}

// ---------------------------------------------------------------------------
// Kernel 2: per-token squared norm (one warp per token)
// ---------------------------------------------------------------------------
__global__ void k_sz() {
    int w    = (blockIdx.x * blockDim.x + threadIdx.x) >> 5;
    int lane = threadIdx.x & 31;
    const float4* row = (const float4*)(g_zf + (size_t)w * D);
    float s = 0.f;
#pragma unroll
    for (int i = 0; i < 2; i++) {
        float4 v = row[lane + 32 * i];
        s += v.x * v.x + v.y * v.y + v.z * v.z + v.w * v.w;
    }
#pragma unroll
    for (int o = 16; o; o >>= 1) s += __shfl_down_sync(0xFFFFFFFFu, s, o);
    if (lane == 0) g_sz[w] = s;
}

// ---------------------------------------------------------------------------
// Kernel 3: per-code squared norm (one warp per code)
// ---------------------------------------------------------------------------
__global__ void k_en(const float* __restrict__ emb) {
    int w    = (blockIdx.x * blockDim.x + threadIdx.x) >> 5;
    int lane = threadIdx.x & 31;
    const float4* row = (const float4*)(emb + (size_t)w * D);
    float s = 0.f;
#pragma unroll
    for (int i = 0; i < 2; i++) {
        float4 v = row[lane + 32 * i];
        s += v.x * v.x + v.y * v.y + v.z * v.z + v.w * v.w;
    }
#pragma unroll
    for (int o = 16; o; o >>= 1) s += __shfl_down_sync(0xFFFFFFFFu, s, o);
    if (lane == 0) g_en[w] = s;
}

// ---------------------------------------------------------------------------
// Kernel 4: distances + argmin. 128x128 tile, 8x8 per thread, DK=16.
//   d[m][k] = fl( fl(Sz[m] + en[k]) - 2*dot(z_m, e_k) )   (matches reference
//   elementwise rounding; dot accumulated sequentially over d)
//   Tie-break: smallest k (argmin first-index semantics).
// ---------------------------------------------------------------------------
__global__ __launch_bounds__(256, 2) void k_dist(const float* __restrict__ emb) {
    __shared__ float As[16][128];
    __shared__ float Bs[16][128];
    __shared__ float RD[128][17];
    __shared__ int   RK[128][17];

    int tid = threadIdx.x;
    int tx = tid & 15;          // k-dim thread coord
    int ty = tid >> 4;          // m-dim thread coord
    int m0 = blockIdx.x * 128;

    int lm = tid >> 1;          // cooperative-load row (0..127)
    int ld = (tid & 1) * 8;     // cooperative-load d offset (0 or 8)

    float szr[8], bestd[8];
    int bestk[8];
#pragma unroll
    for (int i = 0; i < 8; i++) {
        szr[i]   = g_sz[m0 + ty * 8 + i];
        bestd[i] = 3.4e38f;
        bestk[i] = 0;
    }

    for (int kk = 0; kk < K; kk += 128) {
        float acc[8][8];
#pragma unroll
        for (int i = 0; i < 8; i++)
#pragma unroll
            for (int j = 0; j < 8; j++) acc[i][j] = 0.f;

        for (int d0 = 0; d0 < D; d0 += 16) {
            float4 a0 = *(const float4*)&g_zf[(size_t)(m0 + lm) * D + d0 + ld];
            float4 a1 = *(const float4*)&g_zf[(size_t)(m0 + lm) * D + d0 + ld + 4];
            float4 b0 = *(const float4*)&emb[(size_t)(kk + lm) * D + d0 + ld];
            float4 b1 = *(const float4*)&emb[(size_t)(kk + lm) * D + d0 + ld + 4];
            __syncthreads();   // previous tile fully consumed
            As[ld + 0][lm] = a0.x; As[ld + 1][lm] = a0.y;
            As[ld + 2][lm] = a0.z; As[ld + 3][lm] = a0.w;
            As[ld + 4][lm] = a1.x; As[ld + 5][lm] = a1.y;
            As[ld + 6][lm] = a1.z; As[ld + 7][lm] = a1.w;
            Bs[ld + 0][lm] = b0.x; Bs[ld + 1][lm] = b0.y;
            Bs[ld + 2][lm] = b0.z; Bs[ld + 3][lm] = b0.w;
            Bs[ld + 4][lm] = b1.x; Bs[ld + 5][lm] = b1.y;
            Bs[ld + 6][lm] = b1.z; Bs[ld + 7][lm] = b1.w;
            __syncthreads();
#pragma unroll
            for (int dd = 0; dd < 16; dd++) {
                float a[8], b[8];
#pragma unroll
                for (int j = 0; j < 8; j++) {
                    a[j] = As[dd][ty * 8 + j];
                    b[j] = Bs[dd][tx * 8 + j];
                }
#pragma unroll
                for (int i = 0; i < 8; i++)
#pragma unroll
                    for (int j = 0; j < 8; j++)
                        acc[i][j] = fmaf(a[i], b[j], acc[i][j]);
            }
        }

        float enr[8];
#pragma unroll
        for (int j = 0; j < 8; j++) enr[j] = g_en[kk + tx * 8 + j];
#pragma unroll
        for (int i = 0; i < 8; i++) {
#pragma unroll
            for (int j = 0; j < 8; j++) {
                float s  = szr[i] + enr[j];        // fl(a+b) as in reference
                float dv = s - 2.0f * acc[i][j];   // 2c exact; one rounding
                int   k  = kk + tx * 8 + j;
                if (dv < bestd[i]) { bestd[i] = dv; bestk[i] = k; }
            }
        }
    }

    __syncthreads();
#pragma unroll
    for (int i = 0; i < 8; i++) {
        RD[ty * 8 + i][tx] = bestd[i];
        RK[ty * 8 + i][tx] = bestk[i];
    }
    __syncthreads();
    if (tid < 128) {
        float bd = 3.4e38f;
        int   bk = 0x7FFFFFFF;
#pragma unroll
        for (int c = 0; c < 16; c++) {
            float v  = RD[tid][c];
            int   k2 = RK[tid][c];
            if (v < bd || (v == bd && k2 < bk)) { bd = v; bk = k2; }
        }
        g_idx[m0 + tid] = bk;
    }
}

// ---------------------------------------------------------------------------
// Kernel 5: write indices (as float, reference tuple element 0)
// ---------------------------------------------------------------------------
__global__ void k_out_idx(float* __restrict__ out) {
    int n = blockIdx.x * blockDim.x + threadIdx.x;
    out[n] = (float)g_idx[n];
}

// ---------------------------------------------------------------------------
// Kernel 6: gather z_q back to NCHW (coalesced writes)
// ---------------------------------------------------------------------------
__global__ void k_out_zq(const float* __restrict__ emb, float* __restrict__ out) {
    int t  = blockIdx.x * blockDim.x + threadIdx.x;   // over B*D*HW
    int hw = t & (HW - 1);
    int c  = (t >> 12) & (D - 1);
    int b  = t >> 20;
    int idx = g_idx[b * HW + hw];
    out[t] = emb[idx * D + c];
}

// ---------------------------------------------------------------------------
extern "C" void kernel_launch(void* const* d_in, const int* in_sizes, int n_in,
                              void* d_out, int out_size) {
    const float* z   = (const float*)d_in[0];
    const float* emb = (const float*)d_in[1];
    float* out = (float*)d_out;

    dim3 tb(32, 8);
    k_transpose<<<dim3(HW / 32, D / 32, B_), tb>>>(z);
    k_sz<<<N_TOK / 8, 256>>>();
    k_en<<<K / 8, 256>>>(emb);
    k_dist<<<N_TOK / 128, 256>>>(emb);
    k_out_idx<<<N_TOK / 256, 256>>>(out);
    k_out_zq<<<(B_ * D * HW) / 256, 256>>>(emb, out + N_TOK);
}